// round 2
// baseline (speedup 1.0000x reference)
#include <cuda_runtime.h>
#include <math.h>

#define TT 8
#define NN 50000
#define EE 800000
#define FF 128
#define HH 128

// ---------------- device scratch (no allocations allowed) ----------------
__device__ float g_agg[NN * HH];          // aggregated neighbor features (pre-scaled by 1/cnt)
__device__ float g_hA[NN * HH];           // ping buffer
__device__ float g_hB[NN * HH];           // pong buffer
__device__ int   g_cnt[TT * NN];          // in-degree per node per t
__device__ int   g_rowstart[TT * (NN + 1)];
__device__ int   g_cursor[TT * NN];
__device__ float g_invcnt[TT * NN];       // 1/max(cnt,1)
__device__ int   g_csrsrc[TT * EE];       // CSR (by dst) source node ids
__device__ float g_pooled[TT * HH];       // column sums of final layer (divide by N later)

// ---------------- setup kernels ----------------
__global__ void zero_kernel() {
    int stride = gridDim.x * blockDim.x;
    for (int i = blockIdx.x * blockDim.x + threadIdx.x; i < TT * NN; i += stride) g_cnt[i] = 0;
    for (int i = blockIdx.x * blockDim.x + threadIdx.x; i < TT * HH; i += stride) g_pooled[i] = 0.0f;
}

__global__ void count_kernel(const int* __restrict__ ei) {
    int idx = blockIdx.x * blockDim.x + threadIdx.x;
    if (idx >= TT * EE) return;
    int t = idx / EE, e = idx - t * EE;
    int dst = ei[(size_t)t * 2 * EE + EE + e];
    atomicAdd(&g_cnt[t * NN + dst], 1);
}

// one block per timestep: exclusive scan of degrees -> row_start, cursor, inv_cnt
__global__ void scan_kernel() {
    int t = blockIdx.x;
    __shared__ int sd[1024];
    int tid = threadIdx.x;
    int carry = 0;
    const int* cnt = g_cnt + t * NN;
    int* rs  = g_rowstart + t * (NN + 1);
    int* cur = g_cursor + t * NN;
    float* ic = g_invcnt + t * NN;
    for (int base = 0; base < NN; base += 1024) {
        int i = base + tid;
        int v = (i < NN) ? cnt[i] : 0;
        if (i < NN) ic[i] = 1.0f / (float)max(v, 1);
        sd[tid] = v;
        __syncthreads();
        for (int off = 1; off < 1024; off <<= 1) {
            int add = (tid >= off) ? sd[tid - off] : 0;
            __syncthreads();
            sd[tid] += add;
            __syncthreads();
        }
        int excl = sd[tid] - v;
        if (i < NN) { rs[i] = carry + excl; cur[i] = carry + excl; }
        carry += sd[1023];
        __syncthreads();
    }
    if (tid == 0) rs[NN] = carry;
}

__global__ void fill_kernel(const int* __restrict__ ei) {
    int idx = blockIdx.x * blockDim.x + threadIdx.x;
    if (idx >= TT * EE) return;
    int t = idx / EE, e = idx - t * EE;
    int src = ei[(size_t)t * 2 * EE + e];
    int dst = ei[(size_t)t * 2 * EE + EE + e];
    int pos = atomicAdd(&g_cursor[t * NN + dst], 1);
    g_csrsrc[(size_t)t * EE + pos] = src;
}

// ---------------- aggregation: one warp per node, pull-gather (no atomics) ----
__global__ void agg_kernel(const float* __restrict__ xs_t, int xsel, int t) {
    const float* x = (xsel == 0) ? xs_t : ((xsel == 1) ? g_hA : g_hB);
    int gw = (blockIdx.x * blockDim.x + threadIdx.x) >> 5;
    int lane = threadIdx.x & 31;
    if (gw >= NN) return;
    const int* rs  = g_rowstart + t * (NN + 1);
    const int* csr = g_csrsrc + (size_t)t * EE;
    int a = rs[gw], b = rs[gw + 1];
    float4 s0 = make_float4(0.f, 0.f, 0.f, 0.f);
    float4 s1 = make_float4(0.f, 0.f, 0.f, 0.f);
    int j = a;
    for (; j + 1 < b; j += 2) {
        int i0 = csr[j], i1 = csr[j + 1];
        float4 v0 = *(const float4*)(x + (size_t)i0 * HH + lane * 4);
        float4 v1 = *(const float4*)(x + (size_t)i1 * HH + lane * 4);
        s0.x += v0.x; s0.y += v0.y; s0.z += v0.z; s0.w += v0.w;
        s1.x += v1.x; s1.y += v1.y; s1.z += v1.z; s1.w += v1.w;
    }
    if (j < b) {
        int i0 = csr[j];
        float4 v0 = *(const float4*)(x + (size_t)i0 * HH + lane * 4);
        s0.x += v0.x; s0.y += v0.y; s0.z += v0.z; s0.w += v0.w;
    }
    float ic = g_invcnt[t * NN + gw];
    float4 o;
    o.x = (s0.x + s1.x) * ic; o.y = (s0.y + s1.y) * ic;
    o.z = (s0.z + s1.z) * ic; o.w = (s0.w + s1.w) * ic;
    *(float4*)(g_agg + (size_t)gw * HH + lane * 4) = o;
}

// ---------------- fused dual GEMM: out = relu([agg|x] @ [Wl;Wr] + b) -----------
// M tile 128, N = 128 (full), K = 256. 256 threads, 8x8 micro-tile (split 4+4).
#define GEMM_SMEM_FLOATS (256 * 128 + 128 * 36 + 128)

__global__ void __launch_bounds__(256, 1)
gemm_kernel(const float* __restrict__ xs_t, int xsel, int osel,
            const float* __restrict__ Wl, const float* __restrict__ Wr,
            const float* __restrict__ bias, int t, int do_pool) {
    const float* x = (xsel == 0) ? xs_t : ((xsel == 1) ? g_hA : g_hB);
    float* out = (osel == 1) ? g_hA : g_hB;

    extern __shared__ float sm[];
    float* w_sh = sm;                    // [256][128]
    float* a_sh = sm + 256 * 128;        // [128][36] (k padded 32->36)
    float* psum = a_sh + 128 * 36;       // [128]

    int tid = threadIdx.x;
    int tx = tid & 15, ty = tid >> 4;
    int row0 = blockIdx.x * 128;
    int c0a = tx * 4, c0b = 64 + tx * 4;

    // stage W' = [Wl ; Wr] into smem, coalesced
    for (int i = tid; i < 256 * 128 / 4; i += 256) {
        int idx = i * 4;
        int k = idx >> 7, c = idx & 127;
        const float* Wsrc = (k < 128) ? (Wl + k * 128 + c) : (Wr + (k - 128) * 128 + c);
        *(float4*)&w_sh[idx] = *(const float4*)Wsrc;
    }

    int rrow[8];
#pragma unroll
    for (int r = 0; r < 8; r++) rrow[r] = (r < 4) ? (ty * 4 + r) : (64 + ty * 4 + r - 4);

    float acc[8][8];
#pragma unroll
    for (int r = 0; r < 8; r++)
#pragma unroll
        for (int c = 0; c < 8; c++) acc[r][c] = 0.0f;

    __syncthreads();

    for (int kc = 0; kc < 8; kc++) {
        int kg0 = kc * 32;
        const float* src = (kg0 < 128) ? g_agg : x;
        int kofs = kg0 & 127;
        // stage A chunk: 128 rows x 32 k
#pragma unroll
        for (int i = 0; i < 4; i++) {
            int task = i * 256 + tid;
            int row = task >> 3, kq = task & 7;
            int grow = row0 + row;
            float4 v = make_float4(0.f, 0.f, 0.f, 0.f);
            if (grow < NN) v = *(const float4*)(src + (size_t)grow * 128 + kofs + kq * 4);
            *(float4*)&a_sh[row * 36 + kq * 4] = v;
        }
        __syncthreads();
#pragma unroll
        for (int k4 = 0; k4 < 8; k4++) {
            float4 A[8];
#pragma unroll
            for (int r = 0; r < 8; r++) A[r] = *(const float4*)&a_sh[rrow[r] * 36 + k4 * 4];
#pragma unroll
            for (int i = 0; i < 4; i++) {
                int k = kg0 + k4 * 4 + i;
                float4 W0 = *(const float4*)&w_sh[k * 128 + c0a];
                float4 W1 = *(const float4*)&w_sh[k * 128 + c0b];
#pragma unroll
                for (int r = 0; r < 8; r++) {
                    float av = (i == 0) ? A[r].x : (i == 1) ? A[r].y : (i == 2) ? A[r].z : A[r].w;
                    acc[r][0] += av * W0.x; acc[r][1] += av * W0.y;
                    acc[r][2] += av * W0.z; acc[r][3] += av * W0.w;
                    acc[r][4] += av * W1.x; acc[r][5] += av * W1.y;
                    acc[r][6] += av * W1.z; acc[r][7] += av * W1.w;
                }
            }
        }
        __syncthreads();
    }

    // epilogue: bias + relu + store (+ fused column-sum pooling on last layer)
    float bc[8];
#pragma unroll
    for (int j = 0; j < 4; j++) { bc[j] = bias[c0a + j]; bc[4 + j] = bias[c0b + j]; }

    float colsum[8];
#pragma unroll
    for (int c = 0; c < 8; c++) colsum[c] = 0.0f;

#pragma unroll
    for (int r = 0; r < 8; r++) {
        int grow = row0 + rrow[r];
        if (grow < NN) {
            float v[8];
#pragma unroll
            for (int c = 0; c < 8; c++) v[c] = fmaxf(acc[r][c] + bc[c], 0.0f);
            *(float4*)(out + (size_t)grow * 128 + c0a) = make_float4(v[0], v[1], v[2], v[3]);
            *(float4*)(out + (size_t)grow * 128 + c0b) = make_float4(v[4], v[5], v[6], v[7]);
            if (do_pool) {
#pragma unroll
                for (int c = 0; c < 8; c++) colsum[c] += v[c];
            }
        }
    }

    if (do_pool) {
        if (tid < 128) psum[tid] = 0.0f;
        __syncthreads();
#pragma unroll
        for (int c = 0; c < 4; c++) {
            atomicAdd(&psum[c0a + c], colsum[c]);
            atomicAdd(&psum[c0b + c], colsum[4 + c]);
        }
        __syncthreads();
        if (tid < 128) atomicAdd(&g_pooled[t * 128 + tid], psum[tid]);
    }
}

// ---------------- attention + head (tiny, one block) -------------------------
__global__ void attn_kernel(const float* __restrict__ Wq, const float* __restrict__ bq,
                            const float* __restrict__ Wk, const float* __restrict__ bk,
                            const float* __restrict__ Wv, const float* __restrict__ bv,
                            const float* __restrict__ Wo, const float* __restrict__ bo,
                            const float* __restrict__ Wh1, const float* __restrict__ bh1,
                            const float* __restrict__ Wh2, const float* __restrict__ bh2,
                            float* __restrict__ outp) {
    __shared__ float seq[TT][HH];
    __shared__ float q7[HH];
    __shared__ float kk[TT][HH];
    __shared__ float vv[TT][HH];
    __shared__ float att[4][TT];
    __shared__ float o7[HH];
    __shared__ float z[HH];
    __shared__ float h1s[64];
    int tid = threadIdx.x;  // 256 threads

    for (int i = tid; i < TT * HH; i += 256) seq[i / HH][i % HH] = g_pooled[i] * (1.0f / (float)NN);
    __syncthreads();

    if (tid < HH) {
        float s = bq[tid];
        for (int k2 = 0; k2 < HH; k2++) s += seq[TT - 1][k2] * Wq[k2 * HH + tid];
        q7[tid] = s;
    }
    for (int i = tid; i < TT * HH; i += 256) {
        int t = i / HH, j = i % HH;
        float sk = bk[j], sv = bv[j];
        for (int k2 = 0; k2 < HH; k2++) {
            float sval = seq[t][k2];
            sk += sval * Wk[k2 * HH + j];
            sv += sval * Wv[k2 * HH + j];
        }
        kk[t][j] = sk; vv[t][j] = sv;
    }
    __syncthreads();

    if (tid < 32) {
        int h = tid >> 3, kt = tid & 7;
        float s = 0.0f;
        for (int d = 0; d < 32; d++) s += q7[h * 32 + d] * kk[kt][h * 32 + d];
        att[h][kt] = s * 0.17677669529663687f;  // 1/sqrt(32)
    }
    __syncthreads();
    if (tid < 4) {
        float m = -1e30f;
        for (int kt = 0; kt < TT; kt++) m = fmaxf(m, att[tid][kt]);
        float e[TT]; float sum = 0.0f;
        for (int kt = 0; kt < TT; kt++) { e[kt] = expf(att[tid][kt] - m); sum += e[kt]; }
        float inv = 1.0f / sum;
        for (int kt = 0; kt < TT; kt++) att[tid][kt] = e[kt] * inv;
    }
    __syncthreads();
    if (tid < HH) {
        int h = tid >> 5;
        float s = 0.0f;
        for (int kt = 0; kt < TT; kt++) s += att[h][kt] * vv[kt][tid];
        o7[tid] = s;
    }
    __syncthreads();
    if (tid < HH) {
        float s = bo[tid];
        for (int k2 = 0; k2 < HH; k2++) s += o7[k2] * Wo[k2 * HH + tid];
        z[tid] = s;
    }
    __syncthreads();
    if (tid < 64) {
        float s = bh1[tid];
        for (int j = 0; j < HH; j++) s += z[j] * Wh1[j * 64 + tid];
        h1s[tid] = fmaxf(s, 0.0f);
    }
    __syncthreads();
    if (tid == 0) {
        float s = bh2[0];
        for (int m = 0; m < 64; m++) s += h1s[m] * Wh2[m];
        outp[0] = 1.0f / (1.0f + expf(-s));
    }
}

// ---------------- host ----------------
extern "C" void kernel_launch(void* const* d_in, const int* in_sizes, int n_in,
                              void* d_out, int out_size) {
    const float* xs  = (const float*)d_in[0];
    const int*   ei  = (const int*)d_in[1];
    const float* Wl1 = (const float*)d_in[2];
    const float* Wr1 = (const float*)d_in[3];
    const float* b1  = (const float*)d_in[4];
    const float* Wl2 = (const float*)d_in[5];
    const float* Wr2 = (const float*)d_in[6];
    const float* b2  = (const float*)d_in[7];
    const float* Wl3 = (const float*)d_in[8];
    const float* Wr3 = (const float*)d_in[9];
    const float* b3  = (const float*)d_in[10];
    const float* Wq  = (const float*)d_in[11];
    const float* bq  = (const float*)d_in[12];
    const float* Wk  = (const float*)d_in[13];
    const float* bk  = (const float*)d_in[14];
    const float* Wv  = (const float*)d_in[15];
    const float* bv  = (const float*)d_in[16];
    const float* Wo  = (const float*)d_in[17];
    const float* bo  = (const float*)d_in[18];
    const float* Wh1 = (const float*)d_in[19];
    const float* bh1 = (const float*)d_in[20];
    const float* Wh2 = (const float*)d_in[21];
    const float* bh2 = (const float*)d_in[22];

    const int smem_bytes = GEMM_SMEM_FLOATS * 4;
    cudaFuncSetAttribute(gemm_kernel, cudaFuncAttributeMaxDynamicSharedMemorySize, smem_bytes);

    zero_kernel<<<256, 256>>>();
    int nbE = (TT * EE + 255) / 256;
    count_kernel<<<nbE, 256>>>(ei);
    scan_kernel<<<TT, 1024>>>();
    fill_kernel<<<nbE, 256>>>(ei);

    int aggBlocks = (NN * 32 + 255) / 256;
    int gemmBlocks = (NN + 127) / 128;

    for (int t = 0; t < TT; t++) {
        const float* xs_t = xs + (size_t)t * NN * FF;
        // layer 1: x = xs (sel 0) -> hA (sel 1)
        agg_kernel<<<aggBlocks, 256>>>(xs_t, 0, t);
        gemm_kernel<<<gemmBlocks, 256, smem_bytes>>>(xs_t, 0, 1, Wl1, Wr1, b1, t, 0);
        // layer 2: hA -> hB
        agg_kernel<<<aggBlocks, 256>>>(xs_t, 1, t);
        gemm_kernel<<<gemmBlocks, 256, smem_bytes>>>(xs_t, 1, 2, Wl2, Wr2, b2, t, 0);
        // layer 3: hB -> hA, with fused pooling
        agg_kernel<<<aggBlocks, 256>>>(xs_t, 2, t);
        gemm_kernel<<<gemmBlocks, 256, smem_bytes>>>(xs_t, 2, 1, Wl3, Wr3, b3, t, 1);
    }

    attn_kernel<<<1, 256>>>(Wq, bq, Wk, bk, Wv, bv, Wo, bo, Wh1, bh1, Wh2, bh2,
                            (float*)d_out);
}

// round 3
// speedup vs baseline: 1.5881x; 1.5881x over previous
#include <cuda_runtime.h>
#include <cuda_bf16.h>
#include <math.h>

#define TT 8
#define NN 50000
#define EE 800000
#define FF 128
#define HH 128
#define WS 136

__device__ __nv_bfloat16 g_xbf[(size_t)TT * NN * HH];
__device__ float         g_agg[NN * HH];
__device__ __nv_bfloat16 g_hA[NN * HH];
__device__ __nv_bfloat16 g_hB[NN * HH];
__device__ int   g_cnt[TT * NN];
__device__ int   g_rowstart[TT * (NN + 1)];
__device__ int   g_cursor[TT * NN];
__device__ float g_invcnt[TT * NN];
__device__ int   g_csrsrc[TT * EE];
__device__ float g_pooled[TT * HH];

__device__ __forceinline__ unsigned f2tf(float f) {
    unsigned r;
    asm("cvt.rna.tf32.f32 %0, %1;" : "=r"(r) : "f"(f));
    return r;
}

__device__ __forceinline__ void mma_tf32(float* c, const unsigned* a, const unsigned* b) {
    asm volatile(
        "mma.sync.aligned.m16n8k8.row.col.f32.tf32.tf32.f32 "
        "{%0,%1,%2,%3}, {%4,%5,%6,%7}, {%8,%9}, {%0,%1,%2,%3};"
        : "+f"(c[0]), "+f"(c[1]), "+f"(c[2]), "+f"(c[3])
        : "r"(a[0]), "r"(a[1]), "r"(a[2]), "r"(a[3]), "r"(b[0]), "r"(b[1]));
}

__global__ void zero_kernel() {
    int stride = gridDim.x * blockDim.x;
    for (int i = blockIdx.x * blockDim.x + threadIdx.x; i < TT * NN; i += stride) g_cnt[i] = 0;
    for (int i = blockIdx.x * blockDim.x + threadIdx.x; i < TT * HH; i += stride) g_pooled[i] = 0.0f;
}

__global__ void xconv_kernel(const float* __restrict__ xs) {
    size_t task = (size_t)blockIdx.x * blockDim.x + threadIdx.x;
    size_t total = (size_t)TT * NN * HH / 4;
    if (task >= total) return;
    float4 v = *(const float4*)(xs + task * 4);
    *(__nv_bfloat162*)(g_xbf + task * 4)     = __floats2bfloat162_rn(v.x, v.y);
    *(__nv_bfloat162*)(g_xbf + task * 4 + 2) = __floats2bfloat162_rn(v.z, v.w);
}

__global__ void count_kernel(const int* __restrict__ ei) {
    int idx = blockIdx.x * blockDim.x + threadIdx.x;
    if (idx >= TT * EE) return;
    int t = idx / EE, e = idx - t * EE;
    int dst = ei[(size_t)t * 2 * EE + EE + e];
    atomicAdd(&g_cnt[t * NN + dst], 1);
}

__global__ void scan_kernel() {
    int t = blockIdx.x;
    __shared__ int sd[1024];
    int tid = threadIdx.x;
    int carry = 0;
    const int* cnt = g_cnt + t * NN;
    int* rs  = g_rowstart + t * (NN + 1);
    int* cur = g_cursor + t * NN;
    float* ic = g_invcnt + t * NN;
    for (int base = 0; base < NN; base += 1024) {
        int i = base + tid;
        int v = (i < NN) ? cnt[i] : 0;
        if (i < NN) ic[i] = 1.0f / (float)max(v, 1);
        sd[tid] = v;
        __syncthreads();
        for (int off = 1; off < 1024; off <<= 1) {
            int add = (tid >= off) ? sd[tid - off] : 0;
            __syncthreads();
            sd[tid] += add;
            __syncthreads();
        }
        int excl = sd[tid] - v;
        if (i < NN) { rs[i] = carry + excl; cur[i] = carry + excl; }
        carry += sd[1023];
        __syncthreads();
    }
    if (tid == 0) rs[NN] = carry;
}

__global__ void fill_kernel(const int* __restrict__ ei) {
    int idx = blockIdx.x * blockDim.x + threadIdx.x;
    if (idx >= TT * EE) return;
    int t = idx / EE, e = idx - t * EE;
    int src = ei[(size_t)t * 2 * EE + e];
    int dst = ei[(size_t)t * 2 * EE + EE + e];
    int pos = atomicAdd(&g_cursor[t * NN + dst], 1);
    g_csrsrc[(size_t)t * EE + pos] = src;
}

__global__ void agg_kernel(int xsel, int t) {
    const __nv_bfloat16* x = (xsel == 0) ? (g_xbf + (size_t)t * NN * HH)
                                         : ((xsel == 1) ? g_hA : g_hB);
    int gw = (blockIdx.x * blockDim.x + threadIdx.x) >> 5;
    int lane = threadIdx.x & 31;
    if (gw >= NN) return;
    const int* rs  = g_rowstart + t * (NN + 1);
    const int* csr = g_csrsrc + (size_t)t * EE;
    int a = rs[gw], b = rs[gw + 1];
    float4 s0 = make_float4(0.f, 0.f, 0.f, 0.f);
    float4 s1 = make_float4(0.f, 0.f, 0.f, 0.f);
    int j = a;
    for (; j + 1 < b; j += 2) {
        int i0 = csr[j], i1 = csr[j + 1];
        uint2 u0 = *(const uint2*)(x + (size_t)i0 * HH + lane * 4);
        uint2 u1 = *(const uint2*)(x + (size_t)i1 * HH + lane * 4);
        float2 a0 = __bfloat1622float2(*reinterpret_cast<__nv_bfloat162*>(&u0.x));
        float2 a1 = __bfloat1622float2(*reinterpret_cast<__nv_bfloat162*>(&u0.y));
        float2 b0 = __bfloat1622float2(*reinterpret_cast<__nv_bfloat162*>(&u1.x));
        float2 b1 = __bfloat1622float2(*reinterpret_cast<__nv_bfloat162*>(&u1.y));
        s0.x += a0.x; s0.y += a0.y; s0.z += a1.x; s0.w += a1.y;
        s1.x += b0.x; s1.y += b0.y; s1.z += b1.x; s1.w += b1.y;
    }
    if (j < b) {
        int i0 = csr[j];
        uint2 u0 = *(const uint2*)(x + (size_t)i0 * HH + lane * 4);
        float2 a0 = __bfloat1622float2(*reinterpret_cast<__nv_bfloat162*>(&u0.x));
        float2 a1 = __bfloat1622float2(*reinterpret_cast<__nv_bfloat162*>(&u0.y));
        s0.x += a0.x; s0.y += a0.y; s0.z += a1.x; s0.w += a1.y;
    }
    float ic = g_invcnt[t * NN + gw];
    float4 o;
    o.x = (s0.x + s1.x) * ic; o.y = (s0.y + s1.y) * ic;
    o.z = (s0.z + s1.z) * ic; o.w = (s0.w + s1.w) * ic;
    *(float4*)(g_agg + (size_t)gw * HH + lane * 4) = o;
}

#define GEMM_SMEM_UINTS (256 * WS + 128 * 36)

__global__ void __launch_bounds__(256, 1)
gemm_kernel(int xsel, int osel,
            const float* __restrict__ Wl, const float* __restrict__ Wr,
            const float* __restrict__ bias, int t) {
    const __nv_bfloat16* x = (xsel == 0) ? (g_xbf + (size_t)t * NN * HH)
                                         : ((xsel == 1) ? g_hA : g_hB);
    __nv_bfloat16* out = (osel == 1) ? g_hA : g_hB;

    extern __shared__ unsigned sm_u[];
    unsigned* w_sh = sm_u;
    unsigned* a_sh = sm_u + 256 * WS;

    int tid = threadIdx.x;
    int wid = tid >> 5, lane = tid & 31;
    int wm = wid >> 1, wn = wid & 1;
    int rr = lane >> 2, tg = lane & 3;
    int row0 = blockIdx.x * 128;

    for (int i = tid; i < 256 * 128 / 4; i += 256) {
        int flat = i * 4;
        int k = flat >> 7, c = flat & 127;
        const float* Wsrc = (k < 128) ? (Wl + k * 128 + c) : (Wr + (k - 128) * 128 + c);
        float4 v = *(const float4*)Wsrc;
        *(uint4*)&w_sh[k * WS + c] = make_uint4(f2tf(v.x), f2tf(v.y), f2tf(v.z), f2tf(v.w));
    }

    float acc[2][8][4];
#pragma unroll
    for (int mt = 0; mt < 2; mt++)
#pragma unroll
        for (int nt = 0; nt < 8; nt++)
#pragma unroll
            for (int i = 0; i < 4; i++) acc[mt][nt][i] = 0.0f;

    __syncthreads();

    for (int kc = 0; kc < 8; kc++) {
        int kg0 = kc * 32;
#pragma unroll
        for (int i = 0; i < 4; i++) {
            int task = i * 256 + tid;
            int row = task >> 3, kq = task & 7;
            int grow = row0 + row;
            uint4 u = make_uint4(0u, 0u, 0u, 0u);
            if (grow < NN) {
                if (kg0 < 128) {
                    float4 v = *(const float4*)(g_agg + (size_t)grow * 128 + kg0 + kq * 4);
                    u = make_uint4(f2tf(v.x), f2tf(v.y), f2tf(v.z), f2tf(v.w));
                } else {
                    const __nv_bfloat16* xp = x + (size_t)grow * 128 + (kg0 - 128) + kq * 4;
                    uint2 raw = *(const uint2*)xp;
                    float2 f0 = __bfloat1622float2(*reinterpret_cast<__nv_bfloat162*>(&raw.x));
                    float2 f1 = __bfloat1622float2(*reinterpret_cast<__nv_bfloat162*>(&raw.y));
                    u = make_uint4(__float_as_uint(f0.x), __float_as_uint(f0.y),
                                   __float_as_uint(f1.x), __float_as_uint(f1.y));
                }
            }
            *(uint4*)&a_sh[row * 36 + kq * 4] = u;
        }
        __syncthreads();

#pragma unroll
        for (int ks = 0; ks < 4; ks++) {
            unsigned a[2][4];
#pragma unroll
            for (int mt = 0; mt < 2; mt++) {
                int base = (wm * 32 + mt * 16 + rr) * 36 + ks * 8 + tg;
                a[mt][0] = a_sh[base];
                a[mt][1] = a_sh[base + 8 * 36];
                a[mt][2] = a_sh[base + 4];
                a[mt][3] = a_sh[base + 8 * 36 + 4];
            }
            unsigned b[8][2];
            int kwb = (kg0 + ks * 8 + tg) * WS + wn * 64 + rr;
#pragma unroll
            for (int nt = 0; nt < 8; nt++) {
                b[nt][0] = w_sh[kwb + nt * 8];
                b[nt][1] = w_sh[kwb + 4 * WS + nt * 8];
            }
#pragma unroll
            for (int mt = 0; mt < 2; mt++)
#pragma unroll
                for (int nt = 0; nt < 8; nt++)
                    mma_tf32(acc[mt][nt], a[mt], b[nt]);
        }
        __syncthreads();
    }

#pragma unroll
    for (int nt = 0; nt < 8; nt++) {
        int ncol = wn * 64 + nt * 8 + tg * 2;
        float2 bb = *(const float2*)(bias + ncol);
#pragma unroll
        for (int mt = 0; mt < 2; mt++) {
            int r = row0 + wm * 32 + mt * 16 + rr;
            float v0 = fmaxf(acc[mt][nt][0] + bb.x, 0.0f);
            float v1 = fmaxf(acc[mt][nt][1] + bb.y, 0.0f);
            float v2 = fmaxf(acc[mt][nt][2] + bb.x, 0.0f);
            float v3 = fmaxf(acc[mt][nt][3] + bb.y, 0.0f);
            if (r < NN)
                *(__nv_bfloat162*)(out + (size_t)r * 128 + ncol) = __floats2bfloat162_rn(v0, v1);
            if (r + 8 < NN)
                *(__nv_bfloat162*)(out + (size_t)(r + 8) * 128 + ncol) = __floats2bfloat162_rn(v2, v3);
        }
    }
}

#define POOL_BLKS 32
__global__ void pool_kernel(int t) {
    int blk = blockIdx.x;
    int c = threadIdx.x & 127;
    int half = threadIdx.x >> 7;
    const int chunk = (NN + POOL_BLKS - 1) / POOL_BLKS;
    int r0 = blk * chunk;
    int r1 = min(r0 + chunk, NN);
    float s = 0.0f;
    for (int r = r0 + half; r < r1; r += 2)
        s += __bfloat162float(g_hA[(size_t)r * 128 + c]);
    atomicAdd(&g_pooled[t * 128 + c], s);
}

__global__ void attn_kernel(const float* __restrict__ Wq, const float* __restrict__ bq,
                            const float* __restrict__ Wk, const float* __restrict__ bk,
                            const float* __restrict__ Wv, const float* __restrict__ bv,
                            const float* __restrict__ Wo, const float* __restrict__ bo,
                            const float* __restrict__ Wh1, const float* __restrict__ bh1,
                            const float* __restrict__ Wh2, const float* __restrict__ bh2,
                            float* __restrict__ outp) {
    __shared__ float seq[TT][HH];
    __shared__ float q7[HH];
    __shared__ float kk[TT][HH];
    __shared__ float vv[TT][HH];
    __shared__ float att[4][TT];
    __shared__ float o7[HH];
    __shared__ float z[HH];
    __shared__ float h1s[64];
    int tid = threadIdx.x;

    for (int i = tid; i < TT * HH; i += 256) seq[i / HH][i % HH] = g_pooled[i] * (1.0f / (float)NN);
    __syncthreads();

    if (tid < HH) {
        float s = bq[tid];
        for (int k2 = 0; k2 < HH; k2++) s += seq[TT - 1][k2] * Wq[k2 * HH + tid];
        q7[tid] = s;
    }
    for (int i = tid; i < TT * HH; i += 256) {
        int t = i / HH, j = i % HH;
        float sk = bk[j], sv = bv[j];
        for (int k2 = 0; k2 < HH; k2++) {
            float sval = seq[t][k2];
            sk += sval * Wk[k2 * HH + j];
            sv += sval * Wv[k2 * HH + j];
        }
        kk[t][j] = sk; vv[t][j] = sv;
    }
    __syncthreads();

    if (tid < 32) {
        int h = tid >> 3, kt = tid & 7;
        float s = 0.0f;
        for (int d = 0; d < 32; d++) s += q7[h * 32 + d] * kk[kt][h * 32 + d];
        att[h][kt] = s * 0.17677669529663687f;
    }
    __syncthreads();
    if (tid < 4) {
        float m = -1e30f;
        for (int kt = 0; kt < TT; kt++) m = fmaxf(m, att[tid][kt]);
        float e[TT]; float sum = 0.0f;
        for (int kt = 0; kt < TT; kt++) { e[kt] = expf(att[tid][kt] - m); sum += e[kt]; }
        float inv = 1.0f / sum;
        for (int kt = 0; kt < TT; kt++) att[tid][kt] = e[kt] * inv;
    }
    __syncthreads();
    if (tid < HH) {
        int h = tid >> 5;
        float s = 0.0f;
        for (int kt = 0; kt < TT; kt++) s += att[h][kt] * vv[kt][tid];
        o7[tid] = s;
    }
    __syncthreads();
    if (tid < HH) {
        float s = bo[tid];
        for (int k2 = 0; k2 < HH; k2++) s += o7[k2] * Wo[k2 * HH + tid];
        z[tid] = s;
    }
    __syncthreads();
    if (tid < 64) {
        float s = bh1[tid];
        for (int j = 0; j < HH; j++) s += z[j] * Wh1[j * 64 + tid];
        h1s[tid] = fmaxf(s, 0.0f);
    }
    __syncthreads();
    if (tid == 0) {
        float s = bh2[0];
        for (int m = 0; m < 64; m++) s += h1s[m] * Wh2[m];
        outp[0] = 1.0f / (1.0f + expf(-s));
    }
}

extern "C" void kernel_launch(void* const* d_in, const int* in_sizes, int n_in,
                              void* d_out, int out_size) {
    const int*   ei  = (const int*)d_in[1];
    const float* xs  = (const float*)d_in[0];
    const float* Wl1 = (const float*)d_in[2];
    const float* Wr1 = (const float*)d_in[3];
    const float* b1  = (const float*)d_in[4];
    const float* Wl2 = (const float*)d_in[5];
    const float* Wr2 = (const float*)d_in[6];
    const float* b2  = (const float*)d_in[7];
    const float* Wl3 = (const float*)d_in[8];
    const float* Wr3 = (const float*)d_in[9];
    const float* b3  = (const float*)d_in[10];
    const float* Wq  = (const float*)d_in[11];
    const float* bq  = (const float*)d_in[12];
    const float* Wk  = (const float*)d_in[13];
    const float* bk  = (const float*)d_in[14];
    const float* Wv  = (const float*)d_in[15];
    const float* bv  = (const float*)d_in[16];
    const float* Wo  = (const float*)d_in[17];
    const float* bo  = (const float*)d_in[18];
    const float* Wh1 = (const float*)d_in[19];
    const float* bh1 = (const float*)d_in[20];
    const float* Wh2 = (const float*)d_in[21];
    const float* bh2 = (const float*)d_in[22];

    const int smem_bytes = GEMM_SMEM_UINTS * 4;
    cudaFuncSetAttribute(gemm_kernel, cudaFuncAttributeMaxDynamicSharedMemorySize, smem_bytes);

    zero_kernel<<<256, 256>>>();
    {
        size_t total4 = (size_t)TT * NN * HH / 4;
        xconv_kernel<<<(int)((total4 + 255) / 256), 256>>>(xs);
    }
    int nbE = (TT * EE + 255) / 256;
    count_kernel<<<nbE, 256>>>(ei);
    scan_kernel<<<TT, 1024>>>();
    fill_kernel<<<nbE, 256>>>(ei);

    int aggBlocks = (NN * 32 + 255) / 256;
    int gemmBlocks = (NN + 127) / 128;

    for (int t = 0; t < TT; t++) {
        agg_kernel<<<aggBlocks, 256>>>(0, t);
        gemm_kernel<<<gemmBlocks, 256, smem_bytes>>>(0, 1, Wl1, Wr1, b1, t);
        agg_kernel<<<aggBlocks, 256>>>(1, t);
        gemm_kernel<<<gemmBlocks, 256, smem_bytes>>>(1, 2, Wl2, Wr2, b2, t);
        agg_kernel<<<aggBlocks, 256>>>(2, t);
        gemm_kernel<<<gemmBlocks, 256, smem_bytes>>>(2, 1, Wl3, Wr3, b3, t);
        pool_kernel<<<POOL_BLKS, 256>>>(t);
    }

    attn_kernel<<<1, 256>>>(Wq, bq, Wk, bk, Wv, bv, Wo, bo, Wh1, bh1, Wh2, bh2,
                            (float*)d_out);
}

// round 4
// speedup vs baseline: 2.5930x; 1.6328x over previous
#include <cuda_runtime.h>
#include <cuda_fp16.h>
#include <math.h>

#define TT 8
#define NN 50000
#define EE 800000
#define HH 128

__device__ __half g_xh[(size_t)TT * NN * HH];
__device__ __half g_agg[NN * HH];
__device__ __half g_hA[NN * HH];
__device__ __half g_hB[NN * HH];
__device__ __half g_wt[3 * HH * 256];
__device__ __align__(16) int g_cnt[TT * NN];
__device__ int   g_rowstart[TT * (NN + 1)];
__device__ int   g_cursor[TT * NN];
__device__ float g_invcnt[TT * NN];
__device__ int   g_csrsrc[TT * EE];
__device__ float g_pooled[TT * HH];
__device__ int   g_bsum[8 * 49];

#define SCAN_BLK_PER_T 49

__global__ void zero_kernel() {
    int i = blockIdx.x * blockDim.x + threadIdx.x;
    if (i < TT * HH) g_pooled[i] = 0.0f;
    for (int j = i; j < TT * NN; j += gridDim.x * blockDim.x) g_cnt[j] = 0;
}

__global__ void xconv_kernel(const float* __restrict__ xs) {
    size_t task = (size_t)blockIdx.x * blockDim.x + threadIdx.x;
    size_t total = (size_t)TT * NN * HH / 4;
    if (task >= total) return;
    float4 v = *(const float4*)(xs + task * 4);
    *(__half2*)(g_xh + task * 4)     = __floats2half2_rn(v.x, v.y);
    *(__half2*)(g_xh + task * 4 + 2) = __floats2half2_rn(v.z, v.w);
}

__global__ void wconv_kernel(const float* __restrict__ Wl1, const float* __restrict__ Wr1,
                             const float* __restrict__ Wl2, const float* __restrict__ Wr2,
                             const float* __restrict__ Wl3, const float* __restrict__ Wr3) {
    int idx = blockIdx.x * blockDim.x + threadIdx.x;
    if (idx >= 3 * 256 * HH) return;
    int n = idx & 127;
    int k = (idx >> 7) & 255;
    int l = idx >> 15;
    const float* Wl = (l == 0) ? Wl1 : (l == 1) ? Wl2 : Wl3;
    const float* Wr = (l == 0) ? Wr1 : (l == 1) ? Wr2 : Wr3;
    float v = (k < 128) ? Wl[k * HH + n] : Wr[(k - 128) * HH + n];
    g_wt[(l * HH + n) * 256 + k] = __float2half_rn(v);
}

__global__ void count_kernel(const int* __restrict__ ei) {
    int idx = blockIdx.x * blockDim.x + threadIdx.x;
    if (idx >= TT * EE) return;
    int t = idx / EE, e = idx - t * EE;
    int dst = ei[(size_t)t * 2 * EE + EE + e];
    atomicAdd(&g_cnt[t * NN + dst], 1);
}

__global__ void scan1_kernel() {
    int blk = blockIdx.x;
    int t = blk / SCAN_BLK_PER_T, chunk = blk % SCAN_BLK_PER_T;
    int tid = threadIdx.x;
    int i0 = chunk * 1024 + tid * 4;
    int s = 0;
#pragma unroll
    for (int j = 0; j < 4; j++) {
        int i = i0 + j;
        if (i < NN) s += g_cnt[t * NN + i];
    }
#pragma unroll
    for (int off = 16; off > 0; off >>= 1) s += __shfl_down_sync(0xffffffffu, s, off);
    __shared__ int ws[8];
    if ((tid & 31) == 0) ws[tid >> 5] = s;
    __syncthreads();
    if (tid == 0) {
        int tot = 0;
#pragma unroll
        for (int w = 0; w < 8; w++) tot += ws[w];
        g_bsum[blk] = tot;
    }
}

__global__ void scan2_kernel() {
    int w = threadIdx.x;
    if (w >= TT) return;
    int off = 0;
    for (int j = 0; j < SCAN_BLK_PER_T; j++) {
        int idx = w * SCAN_BLK_PER_T + j;
        int v = g_bsum[idx];
        g_bsum[idx] = off;
        off += v;
    }
    g_rowstart[w * (NN + 1) + NN] = off;
}

__global__ void scan3_kernel() {
    int blk = blockIdx.x;
    int t = blk / SCAN_BLK_PER_T, chunk = blk % SCAN_BLK_PER_T;
    int tid = threadIdx.x;
    int lane = tid & 31, wrp = tid >> 5;
    int i0 = chunk * 1024 + tid * 4;
    int c[4];
    int s = 0;
#pragma unroll
    for (int j = 0; j < 4; j++) {
        int i = i0 + j;
        c[j] = (i < NN) ? g_cnt[t * NN + i] : 0;
        s += c[j];
    }
    int sc = s;
#pragma unroll
    for (int off = 1; off < 32; off <<= 1) {
        int v = __shfl_up_sync(0xffffffffu, sc, off);
        if (lane >= off) sc += v;
    }
    __shared__ int ws[8];
    if (lane == 31) ws[wrp] = sc;
    __syncthreads();
    int wexcl = 0;
#pragma unroll
    for (int w = 0; w < 8; w++) if (w < wrp) wexcl += ws[w];
    int run = g_bsum[blk] + wexcl + (sc - s);
    int* rs  = g_rowstart + t * (NN + 1);
    int* cur = g_cursor + t * NN;
    float* ic = g_invcnt + t * NN;
#pragma unroll
    for (int j = 0; j < 4; j++) {
        int i = i0 + j;
        if (i < NN) {
            rs[i] = run;
            cur[i] = run;
            ic[i] = 1.0f / (float)max(c[j], 1);
            run += c[j];
        }
    }
}

__global__ void fill_kernel(const int* __restrict__ ei) {
    int idx = blockIdx.x * blockDim.x + threadIdx.x;
    if (idx >= TT * EE) return;
    int t = idx / EE, e = idx - t * EE;
    int src = ei[(size_t)t * 2 * EE + e];
    int dst = ei[(size_t)t * 2 * EE + EE + e];
    int pos = atomicAdd(&g_cursor[t * NN + dst], 1);
    g_csrsrc[(size_t)t * EE + pos] = src;
}

__global__ void agg_kernel(int xsel, int t) {
    const __half* x = (xsel == 0) ? (g_xh + (size_t)t * NN * HH)
                                  : ((xsel == 1) ? g_hA : g_hB);
    int gw = (blockIdx.x * blockDim.x + threadIdx.x) >> 5;
    int lane = threadIdx.x & 31;
    if (gw >= NN) return;
    const int* rs  = g_rowstart + t * (NN + 1);
    const int* csr = g_csrsrc + (size_t)t * EE;
    int a = rs[gw], b = rs[gw + 1];
    float4 s0 = make_float4(0.f, 0.f, 0.f, 0.f);
    float4 s1 = make_float4(0.f, 0.f, 0.f, 0.f);
    int j = a;
    for (; j + 1 < b; j += 2) {
        int i0 = csr[j], i1 = csr[j + 1];
        uint2 u0 = *(const uint2*)(x + (size_t)i0 * HH + lane * 4);
        uint2 u1 = *(const uint2*)(x + (size_t)i1 * HH + lane * 4);
        float2 a0 = __half22float2(*reinterpret_cast<__half2*>(&u0.x));
        float2 a1 = __half22float2(*reinterpret_cast<__half2*>(&u0.y));
        float2 b0 = __half22float2(*reinterpret_cast<__half2*>(&u1.x));
        float2 b1 = __half22float2(*reinterpret_cast<__half2*>(&u1.y));
        s0.x += a0.x; s0.y += a0.y; s0.z += a1.x; s0.w += a1.y;
        s1.x += b0.x; s1.y += b0.y; s1.z += b1.x; s1.w += b1.y;
    }
    if (j < b) {
        int i0 = csr[j];
        uint2 u0 = *(const uint2*)(x + (size_t)i0 * HH + lane * 4);
        float2 a0 = __half22float2(*reinterpret_cast<__half2*>(&u0.x));
        float2 a1 = __half22float2(*reinterpret_cast<__half2*>(&u0.y));
        s0.x += a0.x; s0.y += a0.y; s0.z += a1.x; s0.w += a1.y;
    }
    float ic = g_invcnt[t * NN + gw];
    __half2 o0 = __floats2half2_rn((s0.x + s1.x) * ic, (s0.y + s1.y) * ic);
    __half2 o1 = __floats2half2_rn((s0.z + s1.z) * ic, (s0.w + s1.w) * ic);
    uint2 o; o.x = *(unsigned*)&o0; o.y = *(unsigned*)&o1;
    *(uint2*)(g_agg + (size_t)gw * HH + lane * 4) = o;
}

#define WKS 264
#define AKS 40
#define GEMM_SMEM_HALFS (128 * WKS + 2 * 128 * AKS)

__device__ __forceinline__ void mma_f16(float* c, const unsigned* a, const unsigned* b) {
    asm volatile(
        "mma.sync.aligned.m16n8k16.row.col.f32.f16.f16.f32 "
        "{%0,%1,%2,%3}, {%4,%5,%6,%7}, {%8,%9}, {%0,%1,%2,%3};"
        : "+f"(c[0]), "+f"(c[1]), "+f"(c[2]), "+f"(c[3])
        : "r"(a[0]), "r"(a[1]), "r"(a[2]), "r"(a[3]), "r"(b[0]), "r"(b[1]));
}

__global__ void __launch_bounds__(256, 2)
gemm_kernel(int xsel, int osel, int layer, const float* __restrict__ bias,
            int t, int do_pool) {
    const __half* x = (xsel == 0) ? (g_xh + (size_t)t * NN * HH)
                                  : ((xsel == 1) ? g_hA : g_hB);
    __half* out = (osel == 1) ? g_hA : g_hB;

    extern __shared__ __half sm_h[];
    __half* w_sh  = sm_h;
    __half* a_sh0 = sm_h + 128 * WKS;
    __half* a_sh1 = a_sh0 + 128 * AKS;

    int tid = threadIdx.x;
    int wid = tid >> 5, lane = tid & 31;
    int wm = wid >> 1, wn = wid & 1;
    int rr = lane >> 2, tg = lane & 3;
    int row0 = blockIdx.x * 128;

    const __half* wbase = g_wt + layer * HH * 256;
#pragma unroll
    for (int it = 0; it < 16; it++) {
        int i = it * 256 + tid;
        int rowp = i >> 5, cc = i & 31;
        uint4 v = *(const uint4*)(wbase + rowp * 256 + cc * 8);
        *(uint4*)&w_sh[rowp * WKS + cc * 8] = v;
    }

    float acc[2][8][4];
#pragma unroll
    for (int mt = 0; mt < 2; mt++)
#pragma unroll
        for (int nt = 0; nt < 8; nt++)
#pragma unroll
            for (int i = 0; i < 4; i++) acc[mt][nt][i] = 0.0f;

    int task0 = tid, task1 = tid + 256;
    int r0t = task0 >> 2, s0t = task0 & 3;
    int r1t = task1 >> 2, s1t = task1 & 3;
    int g0 = row0 + r0t, g1 = row0 + r1t;

    {
        uint4 v0 = make_uint4(0, 0, 0, 0), v1 = make_uint4(0, 0, 0, 0);
        if (g0 < NN) v0 = *(const uint4*)(g_agg + (size_t)g0 * HH + s0t * 8);
        if (g1 < NN) v1 = *(const uint4*)(g_agg + (size_t)g1 * HH + s1t * 8);
        *(uint4*)&a_sh0[r0t * AKS + s0t * 8] = v0;
        *(uint4*)&a_sh0[r1t * AKS + s1t * 8] = v1;
    }
    __syncthreads();

    for (int kc = 0; kc < 8; kc++) {
        __half* a_cur = (kc & 1) ? a_sh1 : a_sh0;
        __half* a_nxt = (kc & 1) ? a_sh0 : a_sh1;

        uint4 v0 = make_uint4(0, 0, 0, 0), v1 = make_uint4(0, 0, 0, 0);
        if (kc < 7) {
            int kg0 = (kc + 1) * 32;
            const __half* src = (kg0 < 128) ? g_agg : x;
            int off = kg0 & 127;
            if (g0 < NN) v0 = *(const uint4*)(src + (size_t)g0 * HH + off + s0t * 8);
            if (g1 < NN) v1 = *(const uint4*)(src + (size_t)g1 * HH + off + s1t * 8);
        }

        int kg = kc * 32;
#pragma unroll
        for (int ks = 0; ks < 2; ks++) {
            int kb = ks * 16;
            unsigned a[2][4];
#pragma unroll
            for (int mt = 0; mt < 2; mt++) {
                int arow = wm * 32 + mt * 16 + rr;
                a[mt][0] = *(const unsigned*)&a_cur[arow * AKS + kb + 2 * tg];
                a[mt][1] = *(const unsigned*)&a_cur[(arow + 8) * AKS + kb + 2 * tg];
                a[mt][2] = *(const unsigned*)&a_cur[arow * AKS + kb + 2 * tg + 8];
                a[mt][3] = *(const unsigned*)&a_cur[(arow + 8) * AKS + kb + 2 * tg + 8];
            }
            unsigned b[8][2];
            int kgl = kg + kb;
#pragma unroll
            for (int nt = 0; nt < 8; nt++) {
                int nrow = wn * 64 + nt * 8 + rr;
                b[nt][0] = *(const unsigned*)&w_sh[nrow * WKS + kgl + 2 * tg];
                b[nt][1] = *(const unsigned*)&w_sh[nrow * WKS + kgl + 2 * tg + 8];
            }
#pragma unroll
            for (int mt = 0; mt < 2; mt++)
#pragma unroll
                for (int nt = 0; nt < 8; nt++)
                    mma_f16(acc[mt][nt], a[mt], b[nt]);
        }

        if (kc < 7) {
            *(uint4*)&a_nxt[r0t * AKS + s0t * 8] = v0;
            *(uint4*)&a_nxt[r1t * AKS + s1t * 8] = v1;
        }
        __syncthreads();
    }

    float colsum[16];
#pragma unroll
    for (int i = 0; i < 16; i++) colsum[i] = 0.0f;

#pragma unroll
    for (int nt = 0; nt < 8; nt++) {
        int ncol = wn * 64 + nt * 8 + tg * 2;
        float2 bb = *(const float2*)(bias + ncol);
#pragma unroll
        for (int mt = 0; mt < 2; mt++) {
            int r = row0 + wm * 32 + mt * 16 + rr;
            float v0 = fmaxf(acc[mt][nt][0] + bb.x, 0.0f);
            float v1 = fmaxf(acc[mt][nt][1] + bb.y, 0.0f);
            float v2 = fmaxf(acc[mt][nt][2] + bb.x, 0.0f);
            float v3 = fmaxf(acc[mt][nt][3] + bb.y, 0.0f);
            if (r < NN) {
                *(__half2*)(out + (size_t)r * HH + ncol) = __floats2half2_rn(v0, v1);
                colsum[nt * 2] += v0; colsum[nt * 2 + 1] += v1;
            }
            if (r + 8 < NN) {
                *(__half2*)(out + (size_t)(r + 8) * HH + ncol) = __floats2half2_rn(v2, v3);
                colsum[nt * 2] += v2; colsum[nt * 2 + 1] += v3;
            }
        }
    }

    if (do_pool) {
        float* psum = (float*)a_sh0;
        if (tid < 128) psum[tid] = 0.0f;
        __syncthreads();
#pragma unroll
        for (int nt = 0; nt < 8; nt++) {
            int ncol = wn * 64 + nt * 8 + tg * 2;
            atomicAdd(&psum[ncol], colsum[nt * 2]);
            atomicAdd(&psum[ncol + 1], colsum[nt * 2 + 1]);
        }
        __syncthreads();
        if (tid < 128) atomicAdd(&g_pooled[t * HH + tid], psum[tid]);
    }
}

__global__ void attn_kernel(const float* __restrict__ Wq, const float* __restrict__ bq,
                            const float* __restrict__ Wk, const float* __restrict__ bk,
                            const float* __restrict__ Wv, const float* __restrict__ bv,
                            const float* __restrict__ Wo, const float* __restrict__ bo,
                            const float* __restrict__ Wh1, const float* __restrict__ bh1,
                            const float* __restrict__ Wh2, const float* __restrict__ bh2,
                            float* __restrict__ outp) {
    __shared__ float seq[TT][HH];
    __shared__ float q7[HH];
    __shared__ float kk[TT][HH];
    __shared__ float vv[TT][HH];
    __shared__ float att[4][TT];
    __shared__ float o7[HH];
    __shared__ float z[HH];
    __shared__ float h1s[64];
    int tid = threadIdx.x;

    for (int i = tid; i < TT * HH; i += 256) seq[i / HH][i % HH] = g_pooled[i] * (1.0f / (float)NN);
    __syncthreads();

    if (tid < HH) {
        float s = bq[tid];
        for (int k2 = 0; k2 < HH; k2++) s += seq[TT - 1][k2] * Wq[k2 * HH + tid];
        q7[tid] = s;
    }
    for (int i = tid; i < TT * HH; i += 256) {
        int t = i / HH, j = i % HH;
        float sk = bk[j], sv = bv[j];
        for (int k2 = 0; k2 < HH; k2++) {
            float sval = seq[t][k2];
            sk += sval * Wk[k2 * HH + j];
            sv += sval * Wv[k2 * HH + j];
        }
        kk[t][j] = sk; vv[t][j] = sv;
    }
    __syncthreads();

    if (tid < 32) {
        int h = tid >> 3, kt = tid & 7;
        float s = 0.0f;
        for (int d = 0; d < 32; d++) s += q7[h * 32 + d] * kk[kt][h * 32 + d];
        att[h][kt] = s * 0.17677669529663687f;
    }
    __syncthreads();
    if (tid < 4) {
        float m = -1e30f;
        for (int kt = 0; kt < TT; kt++) m = fmaxf(m, att[tid][kt]);
        float e[TT]; float sum = 0.0f;
        for (int kt = 0; kt < TT; kt++) { e[kt] = expf(att[tid][kt] - m); sum += e[kt]; }
        float inv = 1.0f / sum;
        for (int kt = 0; kt < TT; kt++) att[tid][kt] = e[kt] * inv;
    }
    __syncthreads();
    if (tid < HH) {
        int h = tid >> 5;
        float s = 0.0f;
        for (int kt = 0; kt < TT; kt++) s += att[h][kt] * vv[kt][tid];
        o7[tid] = s;
    }
    __syncthreads();
    if (tid < HH) {
        float s = bo[tid];
        for (int k2 = 0; k2 < HH; k2++) s += o7[k2] * Wo[k2 * HH + tid];
        z[tid] = s;
    }
    __syncthreads();
    if (tid < 64) {
        float s = bh1[tid];
        for (int j = 0; j < HH; j++) s += z[j] * Wh1[j * 64 + tid];
        h1s[tid] = fmaxf(s, 0.0f);
    }
    __syncthreads();
    if (tid == 0) {
        float s = bh2[0];
        for (int m = 0; m < 64; m++) s += h1s[m] * Wh2[m];
        outp[0] = 1.0f / (1.0f + expf(-s));
    }
}

extern "C" void kernel_launch(void* const* d_in, const int* in_sizes, int n_in,
                              void* d_out, int out_size) {
    const float* xs  = (const float*)d_in[0];
    const int*   ei  = (const int*)d_in[1];
    const float* Wl1 = (const float*)d_in[2];
    const float* Wr1 = (const float*)d_in[3];
    const float* b1  = (const float*)d_in[4];
    const float* Wl2 = (const float*)d_in[5];
    const float* Wr2 = (const float*)d_in[6];
    const float* b2  = (const float*)d_in[7];
    const float* Wl3 = (const float*)d_in[8];
    const float* Wr3 = (const float*)d_in[9];
    const float* b3  = (const float*)d_in[10];
    const float* Wq  = (const float*)d_in[11];
    const float* bq  = (const float*)d_in[12];
    const float* Wk  = (const float*)d_in[13];
    const float* bk  = (const float*)d_in[14];
    const float* Wv  = (const float*)d_in[15];
    const float* bv  = (const float*)d_in[16];
    const float* Wo  = (const float*)d_in[17];
    const float* bo  = (const float*)d_in[18];
    const float* Wh1 = (const float*)d_in[19];
    const float* bh1 = (const float*)d_in[20];
    const float* Wh2 = (const float*)d_in[21];
    const float* bh2 = (const float*)d_in[22];

    const int smem_bytes = GEMM_SMEM_HALFS * 2;
    cudaFuncSetAttribute(gemm_kernel, cudaFuncAttributeMaxDynamicSharedMemorySize, smem_bytes);

    zero_kernel<<<256, 256>>>();
    {
        size_t total4 = (size_t)TT * NN * HH / 4;
        xconv_kernel<<<(int)((total4 + 255) / 256), 256>>>(xs);
    }
    wconv_kernel<<<(3 * 256 * HH + 255) / 256, 256>>>(Wl1, Wr1, Wl2, Wr2, Wl3, Wr3);

    int nbE = (TT * EE + 255) / 256;
    count_kernel<<<nbE, 256>>>(ei);
    scan1_kernel<<<TT * SCAN_BLK_PER_T, 256>>>();
    scan2_kernel<<<1, 32>>>();
    scan3_kernel<<<TT * SCAN_BLK_PER_T, 256>>>();
    fill_kernel<<<nbE, 256>>>(ei);

    int aggBlocks = (NN * 32 + 255) / 256;
    int gemmBlocks = (NN + 127) / 128;

    for (int t = 0; t < TT; t++) {
        agg_kernel<<<aggBlocks, 256>>>(0, t);
        gemm_kernel<<<gemmBlocks, 256, smem_bytes>>>(0, 1, 0, b1, t, 0);
        agg_kernel<<<aggBlocks, 256>>>(1, t);
        gemm_kernel<<<gemmBlocks, 256, smem_bytes>>>(1, 2, 1, b2, t, 0);
        agg_kernel<<<aggBlocks, 256>>>(2, t);
        gemm_kernel<<<gemmBlocks, 256, smem_bytes>>>(2, 1, 2, b3, t, 1);
    }

    attn_kernel<<<1, 256>>>(Wq, bq, Wk, bk, Wv, bv, Wo, bo, Wh1, bh1, Wh2, bh2,
                            (float*)d_out);
}